// round 10
// baseline (speedup 1.0000x reference)
#include <cuda_runtime.h>
#include <cuda_fp16.h>
#include <cstdint>
#include <float.h>

#define NB   8
#define SEQL 1024
#define NH   16
#define HD   64
#define EMB  1024

// ---------------------------------------------------------------------------
// Device scratch (allocation-free rule)
// ---------------------------------------------------------------------------
__device__ __half g_q [NB*NH*SEQL*HD];     // projected Q (fp16, pre-scaled by XSCALE)
__device__ __half g_k [NB*NH*SEQL*HD];     // projected K (fp16)
__device__ __half g_v [NB*NH*SEQL*HD];     // projected V (fp16)
__device__ __half g_ao[NB*SEQL*EMB];       // attention out (fp16) [n][l][e]
__device__ __half g_wo[EMB*EMB];           // Wo fp16
__device__ unsigned g_mb[NB*SEQL*SEQL/32]; // packed mask bits

// log2 domain: softmax(z/32) = exp2(z * C) / sum, C = log2(e)/32, folded into Wq.
#define XSCALE 0.0450842139f          /* 0.03125 * log2(e) */

// ---------------------------------------------------------------------------
// helpers
// ---------------------------------------------------------------------------
__device__ __forceinline__ uint32_t smem_u32(const void* p) {
    uint32_t a;
    asm("{ .reg .u64 t; cvta.to.shared.u64 t, %1; cvt.u32.u64 %0, t; }"
        : "=r"(a) : "l"(p));
    return a;
}

#define SWZ(o) ((o) ^ ((((uint32_t)(o)) >> 3) & 0x70u))

__device__ __forceinline__ void ldsm4(uint32_t r[4], uint32_t a) {
    asm volatile("ldmatrix.sync.aligned.m8n8.x4.shared.b16 {%0,%1,%2,%3}, [%4];"
        : "=r"(r[0]), "=r"(r[1]), "=r"(r[2]), "=r"(r[3]) : "r"(a));
}
__device__ __forceinline__ void ldsm4t(uint32_t r[4], uint32_t a) {
    asm volatile("ldmatrix.sync.aligned.m8n8.x4.trans.shared.b16 {%0,%1,%2,%3}, [%4];"
        : "=r"(r[0]), "=r"(r[1]), "=r"(r[2]), "=r"(r[3]) : "r"(a));
}
__device__ __forceinline__ void mma16816(float* c, const uint32_t* a, const uint32_t* b) {
    asm volatile("mma.sync.aligned.m16n8k16.row.col.f32.f16.f16.f32 "
        "{%0,%1,%2,%3}, {%4,%5,%6,%7}, {%8,%9}, {%0,%1,%2,%3};"
        : "+f"(c[0]), "+f"(c[1]), "+f"(c[2]), "+f"(c[3])
        : "r"(a[0]), "r"(a[1]), "r"(a[2]), "r"(a[3]), "r"(b[0]), "r"(b[1]));
}
__device__ __forceinline__ uint32_t h2ex2(uint32_t x) {
    uint32_t r;
    asm("ex2.approx.f16x2 %0, %1;" : "=r"(r) : "r"(x));
    return r;
}
__device__ __forceinline__ uint32_t packh2(float a, float b) {
    __half2 h = __floats2half2_rn(a, b);
    return *reinterpret_cast<uint32_t*>(&h);
}

#define CPA16(dst, src) \
    asm volatile("cp.async.cg.shared.global [%0], [%1], 16;" \
        :: "r"((uint32_t)(dst)), "l"((const void*)(src)) : "memory")
#define CPC()  asm volatile("cp.async.commit_group;" ::: "memory")
#define CPW0() asm volatile("cp.async.wait_group 0;" ::: "memory")
#define CPW1() asm volatile("cp.async.wait_group 1;" ::: "memory")

// ---------------------------------------------------------------------------
// mask bit-packing: int4 loads + shuffle nibble gather
// ---------------------------------------------------------------------------
__global__ __launch_bounds__(256) void pack_mask(const int* __restrict__ mask) {
    size_t base = ((size_t)blockIdx.x * 256 + threadIdx.x) * 4;
    int4 v = *reinterpret_cast<const int4*>(mask + base);
    uint32_t nib = (uint32_t)(v.x != 0) | ((uint32_t)(v.y != 0) << 1)
                 | ((uint32_t)(v.z != 0) << 2) | ((uint32_t)(v.w != 0) << 3);
    nib |= __shfl_xor_sync(0xffffffffu, nib, 1) << 4;
    nib |= __shfl_xor_sync(0xffffffffu, nib, 2) << 8;
    nib |= __shfl_xor_sync(0xffffffffu, nib, 4) << 16;
    if ((threadIdx.x & 7) == 0) g_mb[base >> 5] = nib;
}

__global__ __launch_bounds__(256) void conv_wo(const float* __restrict__ wo) {
    size_t i = ((size_t)blockIdx.x * 256 + threadIdx.x) * 4;
    float4 f = *reinterpret_cast<const float4*>(wo + i);
    uint32_t u0 = packh2(f.x, f.y), u1 = packh2(f.z, f.w);
    *reinterpret_cast<uint2*>(g_wo + i) = make_uint2(u0, u1);
}

// ---------------------------------------------------------------------------
// QKV projection (pure fp16, 1-term): (131072 x 64) @ (64 x 64)^T
// grid (1024, 3), 256 threads. smem: A 16K | W 8K = 24K
// ---------------------------------------------------------------------------
#define PROJ_SMEM 24576

__global__ __launch_bounds__(256) void proj_mma(
    const float* __restrict__ vin, const float* __restrict__ kin,
    const float* __restrict__ qin,
    const float* __restrict__ Wv, const float* __restrict__ Wk,
    const float* __restrict__ Wq)
{
    extern __shared__ char smc[];
    const uint32_t sb = smem_u32(smc);
    const uint32_t AS = sb, WS = sb + 16384;

    const int which = blockIdx.y;
    const float* in = (which == 0) ? vin : (which == 1) ? kin : qin;
    const float* W  = (which == 0) ? Wv  : (which == 1) ? Wk  : Wq;
    __half* outp    = (which == 0) ? g_v : (which == 1) ? g_k : g_q;
    const float wscale = (which == 2) ? XSCALE : 1.0f;

    const int m0 = blockIdx.x * 128;
    const int tid = threadIdx.x;
    const int w = tid >> 5, L = tid & 31;

    for (int c = tid; c < 1024; c += 256) {
        int r = c >> 3, c0 = (c & 7) * 8;
        const float4* s = reinterpret_cast<const float4*>(in + (size_t)(m0 + r) * 64 + c0);
        float4 f0 = s[0], f1 = s[1];
        uint32_t u0 = packh2(f0.x, f0.y), u1 = packh2(f0.z, f0.w);
        uint32_t u2 = packh2(f1.x, f1.y), u3 = packh2(f1.z, f1.w);
        *reinterpret_cast<uint4*>(smc + SWZ(r * 128 + c0 * 2)) = make_uint4(u0, u1, u2, u3);
    }
    for (int c = tid; c < 512; c += 256) {
        int r = c >> 3, c0 = (c & 7) * 8;
        const float4* s = reinterpret_cast<const float4*>(W + (size_t)r * 64 + c0);
        float4 f0 = s[0], f1 = s[1];
        uint32_t u0 = packh2(f0.x * wscale, f0.y * wscale);
        uint32_t u1 = packh2(f0.z * wscale, f0.w * wscale);
        uint32_t u2 = packh2(f1.x * wscale, f1.y * wscale);
        uint32_t u3 = packh2(f1.z * wscale, f1.w * wscale);
        *reinterpret_cast<uint4*>(smc + 16384 + SWZ(r * 128 + c0 * 2)) = make_uint4(u0, u1, u2, u3);
    }
    __syncthreads();

    float acc[8][4] = {};
    const int lr = (L & 7) + ((L >> 3) & 1) * 8;
    const int lc = ((L >> 4) & 1) * 16;
    const int br = ((L >> 4) & 1) * 8 + (L & 7);
    const int bc = ((L >> 3) & 1) * 16;

    #pragma unroll
    for (int ks = 0; ks < 4; ks++) {
        uint32_t a[4];
        ldsm4(a, AS + SWZ((w * 16 + lr) * 128 + ks * 32 + lc));
        #pragma unroll
        for (int p = 0; p < 4; p++) {
            uint32_t b[4];
            ldsm4(b, WS + SWZ((p * 16 + br) * 128 + ks * 32 + bc));
            mma16816(acc[2*p],   a, &b[0]);
            mma16816(acc[2*p+1], a, &b[2]);
        }
    }

    const int t4 = L >> 2, t2 = (L & 3) * 2;
    const int r0 = m0 + w * 16 + t4, r1 = r0 + 8;
    size_t b0, b1;
    {
        int h0i = r0 & 15, l0i = (r0 >> 4) & 1023, n0i = r0 >> 14;
        int h1i = r1 & 15, l1i = (r1 >> 4) & 1023, n1i = r1 >> 14;
        b0 = ((size_t)((n0i * 16 + h0i) * 1024 + l0i)) * 64;
        b1 = ((size_t)((n1i * 16 + h1i) * 1024 + l1i)) * 64;
    }
    #pragma unroll
    for (int f = 0; f < 8; f++) {
        int col = f * 8 + t2;
        *reinterpret_cast<uint32_t*>(outp + b0 + col) = packh2(acc[f][0], acc[f][1]);
        *reinterpret_cast<uint32_t*>(outp + b1 + col) = packh2(acc[f][2], acc[f][3]);
    }
}

// ---------------------------------------------------------------------------
// Flash attention: block = (128 q rows, head, batch); 8 warps x 16 rows.
// K-tiles of 64. 3-stage cp.async ring, ONE barrier per tile. Batched ldsm
// groups (4 independent loads, then 8 MMAs) to overlap LDS latency.
// smem: Q 16K | ring 3 x {K 8K, V 8K} = 64K
// ---------------------------------------------------------------------------
#define ATTN_SMEM 65536

__global__ __launch_bounds__(256, 2) void attn_mma()
{
    extern __shared__ char smc[];
    const uint32_t sb = smem_u32(smc);
    const uint32_t QS = sb;
    const uint32_t RING = sb + 16384;

    const int q0 = blockIdx.x * 128;
    const int h  = blockIdx.y;
    const int n  = blockIdx.z;
    const int tid = threadIdx.x;
    const int w = tid >> 5, L = tid & 31;

    const size_t head = (size_t)(n * NH + h) * SEQL * 64;
    const __half* qp = g_q + head;
    const __half* kp = g_k + head;
    const __half* vp = g_v + head;

    // prologue: group0 = Q + tile0; group1 = tile1
    for (int c = tid; c < 1024; c += 256) {
        int r = c >> 3, cb = (c & 7) * 16;
        CPA16(QS + SWZ(r * 128 + cb), (const char*)(qp + (size_t)(q0 + r) * 64) + cb);
    }
    for (int c = tid; c < 512; c += 256) {
        int r = c >> 3, cb = (c & 7) * 16;
        uint32_t off = SWZ(r * 128 + cb);
        size_t go = (size_t)r * 64;
        CPA16(RING + off,        (const char*)(kp + go) + cb);
        CPA16(RING + 8192 + off, (const char*)(vp + go) + cb);
    }
    CPC();
    for (int c = tid; c < 512; c += 256) {
        int r = c >> 3, cb = (c & 7) * 16;
        uint32_t off = SWZ(r * 128 + cb);
        size_t go = (size_t)(64 + r) * 64;
        CPA16(RING + 16384 + off,        (const char*)(kp + go) + cb);
        CPA16(RING + 16384 + 8192 + off, (const char*)(vp + go) + cb);
    }
    CPC();

    float o[8][4] = {};
    float lacc[4] = {};
    uint32_t aq[4][4];
    const uint32_t ones_b[2] = { 0x3C003C00u, 0x3C003C00u };

    const int lr = (L & 7) + ((L >> 3) & 1) * 8;
    const int lc = ((L >> 4) & 1) * 16;
    const int brr = ((L >> 4) & 1) * 8 + (L & 7);
    const int bcc = ((L >> 3) & 1) * 16;
    const int t4 = L >> 2, t2 = (L & 3) * 2;
    const int qa = q0 + w * 16 + t4, qb = qa + 8;

    const unsigned* mrow_a = g_mb + ((size_t)(n * SEQL + qa)) * 32;
    const unsigned* mrow_b = g_mb + ((size_t)(n * SEQL + qb)) * 32;

    int cur = 0, nxt2 = 2;   // kt%3 and (kt+2)%3
    for (int kt = 0; kt < 16; kt++) {
        // group kt must be complete; kt+1 may still be in flight
        if (kt < 15) { CPW1(); } else { CPW0(); }
        __syncthreads();

        // prefetch kt+2 into ring slot (kt+2)%3 == (kt-1)%3 (all warps past
        // the barrier above have finished reading tile kt-1)
        if (kt < 14) {
            uint32_t B = RING + nxt2 * 16384;
            const int k0 = (kt + 2) * 64;
            for (int c = tid; c < 512; c += 256) {
                int r = c >> 3, cb = (c & 7) * 16;
                uint32_t off = SWZ(r * 128 + cb);
                size_t go = (size_t)(k0 + r) * 64;
                CPA16(B + off,        (const char*)(kp + go) + cb);
                CPA16(B + 8192 + off, (const char*)(vp + go) + cb);
            }
            CPC();
        }

        // prefetch mask words (LDG overlaps S-MMA block)
        unsigned wa0 = mrow_a[kt * 2], wa1 = mrow_a[kt * 2 + 1];
        unsigned wb0 = mrow_b[kt * 2], wb1 = mrow_b[kt * 2 + 1];

        if (kt == 0) {
            #pragma unroll
            for (int ks = 0; ks < 4; ks++)
                ldsm4(aq[ks], QS + SWZ((w * 16 + lr) * 128 + ks * 32 + lc));
        }

        const uint32_t KB = RING + cur * 16384;
        const uint32_t VB = KB + 8192;

        // S = Q K^T : per ks, batch 4 independent ldsm then 8 MMAs
        float s[8][4] = {};
        #pragma unroll
        for (int ks = 0; ks < 4; ks++) {
            uint32_t kb0[4], kb1[4], kb2[4], kb3[4];
            ldsm4(kb0, KB + SWZ((0 * 16 + brr) * 128 + ks * 32 + bcc));
            ldsm4(kb1, KB + SWZ((1 * 16 + brr) * 128 + ks * 32 + bcc));
            ldsm4(kb2, KB + SWZ((2 * 16 + brr) * 128 + ks * 32 + bcc));
            ldsm4(kb3, KB + SWZ((3 * 16 + brr) * 128 + ks * 32 + bcc));
            mma16816(s[0], aq[ks], &kb0[0]);
            mma16816(s[1], aq[ks], &kb0[2]);
            mma16816(s[2], aq[ks], &kb1[0]);
            mma16816(s[3], aq[ks], &kb1[2]);
            mma16816(s[4], aq[ks], &kb2[0]);
            mma16816(s[5], aq[ks], &kb2[2]);
            mma16816(s[6], aq[ks], &kb3[0]);
            mma16816(s[7], aq[ks], &kb3[2]);
        }

        // mask-select -> pack -> ex2 (straight-line)
        uint32_t preg[8][2];
        #pragma unroll
        for (int f = 0; f < 8; f++) {
            unsigned wA = (f < 4) ? wa0 : wa1;
            unsigned wB = (f < 4) ? wb0 : wb1;
            int bit = (f & 3) * 8 + t2;
            float xa0 = ((wA >> bit) & 1)       ? s[f][0] : -100.f;
            float xa1 = ((wA >> (bit + 1)) & 1) ? s[f][1] : -100.f;
            float xb0 = ((wB >> bit) & 1)       ? s[f][2] : -100.f;
            float xb1 = ((wB >> (bit + 1)) & 1) ? s[f][3] : -100.f;
            preg[f][0] = h2ex2(packh2(xa0, xa1));
            preg[f][1] = h2ex2(packh2(xb0, xb1));
        }

        // O += P V ; l += P @ ones : per ks, batch 4 ldsm4t then 9 MMAs
        #pragma unroll
        for (int ks = 0; ks < 4; ks++) {
            uint32_t ph[4] = { preg[2*ks][0], preg[2*ks][1],
                               preg[2*ks+1][0], preg[2*ks+1][1] };
            uint32_t vb0[4], vb1[4], vb2[4], vb3[4];
            ldsm4t(vb0, VB + SWZ((ks * 16 + lr) * 128 + 0 * 32 + lc));
            ldsm4t(vb1, VB + SWZ((ks * 16 + lr) * 128 + 1 * 32 + lc));
            ldsm4t(vb2, VB + SWZ((ks * 16 + lr) * 128 + 2 * 32 + lc));
            ldsm4t(vb3, VB + SWZ((ks * 16 + lr) * 128 + 3 * 32 + lc));
            mma16816(lacc, ph, ones_b);
            mma16816(o[0], ph, &vb0[0]);
            mma16816(o[1], ph, &vb0[2]);
            mma16816(o[2], ph, &vb1[0]);
            mma16816(o[3], ph, &vb1[2]);
            mma16816(o[4], ph, &vb2[0]);
            mma16816(o[5], ph, &vb2[2]);
            mma16816(o[6], ph, &vb3[0]);
            mma16816(o[7], ph, &vb3[2]);
        }

        cur = (cur == 2) ? 0 : cur + 1;
        nxt2 = (nxt2 == 2) ? 0 : nxt2 + 1;
    }

    // epilogue: l complete per row; normalize, store
    float ia = 1.0f / lacc[0], ib = 1.0f / lacc[2];
    size_t ba = ((size_t)(n * SEQL + qa)) * EMB + h * 64;
    size_t bb = ((size_t)(n * SEQL + qb)) * EMB + h * 64;
    #pragma unroll
    for (int f = 0; f < 8; f++) {
        int col = f * 8 + t2;
        *reinterpret_cast<uint32_t*>(g_ao + ba + col) = packh2(o[f][0] * ia, o[f][1] * ia);
        *reinterpret_cast<uint32_t*>(g_ao + bb + col) = packh2(o[f][2] * ib, o[f][3] * ib);
    }
}

// ---------------------------------------------------------------------------
// Output projection: (8192 x 1024) @ (1024 x 1024)^T + bias, pure fp16 1-term.
// Tile 128x128, K chunks of 64, cp.async double-buffered.
// ---------------------------------------------------------------------------
#define OUT_SMEM 65536

__global__ __launch_bounds__(256, 2) void outproj_mma(
    const float* __restrict__ bo, float* __restrict__ out)
{
    extern __shared__ char smc[];
    const uint32_t sb = smem_u32(smc);

    const int m0 = blockIdx.x * 128;
    const int e0 = blockIdx.y * 128;
    const int tid = threadIdx.x;
    const int w = tid >> 5, L = tid & 31;

    {
        uint32_t B = sb;
        for (int c = tid; c < 1024; c += 256) {
            int r = c >> 3, cb = (c & 7) * 16;
            uint32_t off = SWZ(r * 128 + cb);
            CPA16(B + off,         (const char*)(g_ao + (size_t)(m0 + r) * EMB) + cb);
            CPA16(B + 16384 + off, (const char*)(g_wo + (size_t)(e0 + r) * EMB) + cb);
        }
        CPC();
    }

    float acc[16][4] = {};
    const int lr = (L & 7) + ((L >> 3) & 1) * 8;
    const int lc = ((L >> 4) & 1) * 16;
    const int brr = ((L >> 4) & 1) * 8 + (L & 7);
    const int bcc = ((L >> 3) & 1) * 16;

    for (int kt = 0; kt < 16; kt++) {
        if (kt < 15) {
            uint32_t B = sb + ((kt + 1) & 1) * 32768;
            const int k0 = (kt + 1) * 64;
            for (int c = tid; c < 1024; c += 256) {
                int r = c >> 3, cb = (c & 7) * 16;
                uint32_t off = SWZ(r * 128 + cb);
                CPA16(B + off,         (const char*)(g_ao + (size_t)(m0 + r) * EMB + k0) + cb);
                CPA16(B + 16384 + off, (const char*)(g_wo + (size_t)(e0 + r) * EMB + k0) + cb);
            }
            CPC();
            CPW1();
        } else {
            CPW0();
        }
        __syncthreads();

        const uint32_t AS = sb + (kt & 1) * 32768;
        const uint32_t BS = AS + 16384;

        #pragma unroll
        for (int ks = 0; ks < 4; ks++) {
            uint32_t a[4];
            ldsm4(a, AS + SWZ((w * 16 + lr) * 128 + ks * 32 + lc));
            #pragma unroll
            for (int p = 0; p < 8; p++) {
                uint32_t b[4];
                ldsm4(b, BS + SWZ((p * 16 + brr) * 128 + ks * 32 + bcc));
                mma16816(acc[2*p],   a, &b[0]);
                mma16816(acc[2*p+1], a, &b[2]);
            }
        }
        __syncthreads();
    }

    const int t4 = L >> 2, t2 = (L & 3) * 2;
    const int r0 = m0 + w * 16 + t4, r1 = r0 + 8;
    #pragma unroll
    for (int f = 0; f < 16; f++) {
        int col = e0 + f * 8 + t2;
        float b0v = bo[col], b1v = bo[col + 1];
        float2 v0 = make_float2(acc[f][0] + b0v, acc[f][1] + b1v);
        float2 v1 = make_float2(acc[f][2] + b0v, acc[f][3] + b1v);
        *reinterpret_cast<float2*>(out + (size_t)r0 * EMB + col) = v0;
        *reinterpret_cast<float2*>(out + (size_t)r1 * EMB + col) = v1;
    }
}

// ---------------------------------------------------------------------------
extern "C" void kernel_launch(void* const* d_in, const int* in_sizes, int n_in,
                              void* d_out, int out_size)
{
    const float* values = (const float*)d_in[0];
    const float* keys   = (const float*)d_in[1];
    const float* query  = (const float*)d_in[2];
    const int*   mask   = (const int*)d_in[3];
    const float* Wv     = (const float*)d_in[4];
    const float* Wk     = (const float*)d_in[5];
    const float* Wq     = (const float*)d_in[6];
    const float* Wo     = (const float*)d_in[7];
    const float* bo     = (const float*)d_in[8];
    float* out = (float*)d_out;
    (void)in_sizes; (void)n_in; (void)out_size;

    cudaFuncSetAttribute(proj_mma,    cudaFuncAttributeMaxDynamicSharedMemorySize, PROJ_SMEM);
    cudaFuncSetAttribute(attn_mma,    cudaFuncAttributeMaxDynamicSharedMemorySize, ATTN_SMEM);
    cudaFuncSetAttribute(outproj_mma, cudaFuncAttributeMaxDynamicSharedMemorySize, OUT_SMEM);

    pack_mask<<<NB*SEQL*SEQL/1024, 256>>>(mask);
    conv_wo<<<EMB*EMB/1024, 256>>>(Wo);
    proj_mma<<<dim3(1024, 3), 256, PROJ_SMEM>>>(values, keys, query, Wv, Wk, Wq);
    attn_mma<<<dim3(SEQL/128, NH, NB), 256, ATTN_SMEM>>>();
    outproj_mma<<<dim3(64, 8), 256, OUT_SMEM>>>(bo, out);
}

// round 11
// speedup vs baseline: 1.3693x; 1.3693x over previous
#include <cuda_runtime.h>
#include <cuda_fp16.h>
#include <cstdint>
#include <float.h>

#define NB   8
#define SEQL 1024
#define NH   16
#define HD   64
#define EMB  1024

// ---------------------------------------------------------------------------
// Device scratch (allocation-free rule)
// ---------------------------------------------------------------------------
__device__ __half g_q [NB*NH*SEQL*HD];     // projected Q (fp16, pre-scaled by XSCALE)
__device__ __half g_k [NB*NH*SEQL*HD];     // projected K (fp16)
__device__ __half g_v [NB*NH*SEQL*HD];     // projected V (fp16)
__device__ __half g_ao[NB*SEQL*EMB];       // attention out (fp16) [n][l][e]
__device__ __half g_wo[EMB*EMB];           // Wo fp16
__device__ unsigned g_mb[NB*SEQL*SEQL/32]; // packed mask bits

// log2 domain: softmax(z/32) = exp2(z * C) / sum, C = log2(e)/32, folded into Wq.
#define XSCALE 0.0450842139f          /* 0.03125 * log2(e) */

// ---------------------------------------------------------------------------
// helpers
// ---------------------------------------------------------------------------
__device__ __forceinline__ uint32_t smem_u32(const void* p) {
    uint32_t a;
    asm("{ .reg .u64 t; cvta.to.shared.u64 t, %1; cvt.u32.u64 %0, t; }"
        : "=r"(a) : "l"(p));
    return a;
}

#define SWZ(o) ((o) ^ ((((uint32_t)(o)) >> 3) & 0x70u))

__device__ __forceinline__ void ldsm4(uint32_t r[4], uint32_t a) {
    asm volatile("ldmatrix.sync.aligned.m8n8.x4.shared.b16 {%0,%1,%2,%3}, [%4];"
        : "=r"(r[0]), "=r"(r[1]), "=r"(r[2]), "=r"(r[3]) : "r"(a));
}
__device__ __forceinline__ void ldsm4t(uint32_t r[4], uint32_t a) {
    asm volatile("ldmatrix.sync.aligned.m8n8.x4.trans.shared.b16 {%0,%1,%2,%3}, [%4];"
        : "=r"(r[0]), "=r"(r[1]), "=r"(r[2]), "=r"(r[3]) : "r"(a));
}
__device__ __forceinline__ void mma16816(float* c, const uint32_t* a, const uint32_t* b) {
    asm volatile("mma.sync.aligned.m16n8k16.row.col.f32.f16.f16.f32 "
        "{%0,%1,%2,%3}, {%4,%5,%6,%7}, {%8,%9}, {%0,%1,%2,%3};"
        : "+f"(c[0]), "+f"(c[1]), "+f"(c[2]), "+f"(c[3])
        : "r"(a[0]), "r"(a[1]), "r"(a[2]), "r"(a[3]), "r"(b[0]), "r"(b[1]));
}
__device__ __forceinline__ uint32_t h2ex2(uint32_t x) {
    uint32_t r;
    asm("ex2.approx.f16x2 %0, %1;" : "=r"(r) : "r"(x));
    return r;
}
__device__ __forceinline__ uint32_t packh2(float a, float b) {
    __half2 h = __floats2half2_rn(a, b);
    return *reinterpret_cast<uint32_t*>(&h);
}

#define CPA16(dst, src) \
    asm volatile("cp.async.cg.shared.global [%0], [%1], 16;" \
        :: "r"((uint32_t)(dst)), "l"((const void*)(src)) : "memory")
#define CPC()  asm volatile("cp.async.commit_group;" ::: "memory")
#define CPW0() asm volatile("cp.async.wait_group 0;" ::: "memory")
#define CPW1() asm volatile("cp.async.wait_group 1;" ::: "memory")

// ---------------------------------------------------------------------------
// mask bit-packing: int4 loads + shuffle nibble gather
// ---------------------------------------------------------------------------
__global__ __launch_bounds__(256) void pack_mask(const int* __restrict__ mask) {
    size_t base = ((size_t)blockIdx.x * 256 + threadIdx.x) * 4;
    int4 v = *reinterpret_cast<const int4*>(mask + base);
    uint32_t nib = (uint32_t)(v.x != 0) | ((uint32_t)(v.y != 0) << 1)
                 | ((uint32_t)(v.z != 0) << 2) | ((uint32_t)(v.w != 0) << 3);
    nib |= __shfl_xor_sync(0xffffffffu, nib, 1) << 4;
    nib |= __shfl_xor_sync(0xffffffffu, nib, 2) << 8;
    nib |= __shfl_xor_sync(0xffffffffu, nib, 4) << 16;
    if ((threadIdx.x & 7) == 0) g_mb[base >> 5] = nib;
}

__global__ __launch_bounds__(256) void conv_wo(const float* __restrict__ wo) {
    size_t i = ((size_t)blockIdx.x * 256 + threadIdx.x) * 4;
    float4 f = *reinterpret_cast<const float4*>(wo + i);
    uint32_t u0 = packh2(f.x, f.y), u1 = packh2(f.z, f.w);
    *reinterpret_cast<uint2*>(g_wo + i) = make_uint2(u0, u1);
}

// ---------------------------------------------------------------------------
// QKV projection (pure fp16, 1-term): (131072 x 64) @ (64 x 64)^T
// grid (1024, 3), 256 threads. smem: A 16K | W 8K = 24K
// ---------------------------------------------------------------------------
#define PROJ_SMEM 24576

__global__ __launch_bounds__(256) void proj_mma(
    const float* __restrict__ vin, const float* __restrict__ kin,
    const float* __restrict__ qin,
    const float* __restrict__ Wv, const float* __restrict__ Wk,
    const float* __restrict__ Wq)
{
    extern __shared__ char smc[];
    const uint32_t sb = smem_u32(smc);
    const uint32_t AS = sb, WS = sb + 16384;

    const int which = blockIdx.y;
    const float* in = (which == 0) ? vin : (which == 1) ? kin : qin;
    const float* W  = (which == 0) ? Wv  : (which == 1) ? Wk  : Wq;
    __half* outp    = (which == 0) ? g_v : (which == 1) ? g_k : g_q;
    const float wscale = (which == 2) ? XSCALE : 1.0f;

    const int m0 = blockIdx.x * 128;
    const int tid = threadIdx.x;
    const int w = tid >> 5, L = tid & 31;

    for (int c = tid; c < 1024; c += 256) {
        int r = c >> 3, c0 = (c & 7) * 8;
        const float4* s = reinterpret_cast<const float4*>(in + (size_t)(m0 + r) * 64 + c0);
        float4 f0 = s[0], f1 = s[1];
        uint32_t u0 = packh2(f0.x, f0.y), u1 = packh2(f0.z, f0.w);
        uint32_t u2 = packh2(f1.x, f1.y), u3 = packh2(f1.z, f1.w);
        *reinterpret_cast<uint4*>(smc + SWZ(r * 128 + c0 * 2)) = make_uint4(u0, u1, u2, u3);
    }
    for (int c = tid; c < 512; c += 256) {
        int r = c >> 3, c0 = (c & 7) * 8;
        const float4* s = reinterpret_cast<const float4*>(W + (size_t)r * 64 + c0);
        float4 f0 = s[0], f1 = s[1];
        uint32_t u0 = packh2(f0.x * wscale, f0.y * wscale);
        uint32_t u1 = packh2(f0.z * wscale, f0.w * wscale);
        uint32_t u2 = packh2(f1.x * wscale, f1.y * wscale);
        uint32_t u3 = packh2(f1.z * wscale, f1.w * wscale);
        *reinterpret_cast<uint4*>(smc + 16384 + SWZ(r * 128 + c0 * 2)) = make_uint4(u0, u1, u2, u3);
    }
    __syncthreads();

    float acc[8][4] = {};
    const int lr = (L & 7) + ((L >> 3) & 1) * 8;
    const int lc = ((L >> 4) & 1) * 16;
    const int br = ((L >> 4) & 1) * 8 + (L & 7);
    const int bc = ((L >> 3) & 1) * 16;

    #pragma unroll
    for (int ks = 0; ks < 4; ks++) {
        uint32_t a[4];
        ldsm4(a, AS + SWZ((w * 16 + lr) * 128 + ks * 32 + lc));
        #pragma unroll
        for (int p = 0; p < 4; p++) {
            uint32_t b[4];
            ldsm4(b, WS + SWZ((p * 16 + br) * 128 + ks * 32 + bc));
            mma16816(acc[2*p],   a, &b[0]);
            mma16816(acc[2*p+1], a, &b[2]);
        }
    }

    const int t4 = L >> 2, t2 = (L & 3) * 2;
    const int r0 = m0 + w * 16 + t4, r1 = r0 + 8;
    size_t b0, b1;
    {
        int h0i = r0 & 15, l0i = (r0 >> 4) & 1023, n0i = r0 >> 14;
        int h1i = r1 & 15, l1i = (r1 >> 4) & 1023, n1i = r1 >> 14;
        b0 = ((size_t)((n0i * 16 + h0i) * 1024 + l0i)) * 64;
        b1 = ((size_t)((n1i * 16 + h1i) * 1024 + l1i)) * 64;
    }
    #pragma unroll
    for (int f = 0; f < 8; f++) {
        int col = f * 8 + t2;
        *reinterpret_cast<uint32_t*>(outp + b0 + col) = packh2(acc[f][0], acc[f][1]);
        *reinterpret_cast<uint32_t*>(outp + b1 + col) = packh2(acc[f][2], acc[f][3]);
    }
}

// ---------------------------------------------------------------------------
// Flash attention (exact R9 structure — known 118.9us): block = (128 q rows,
// head, batch); 8 warps x 16 rows. K-tiles of 64, cp.async double-buffered.
// No-max log2 softmax; l = P @ ones via extra n=8 MMA.
// smem: Q 16K | buf0 {K 8K, V 8K} | buf1 {...} = 48K
// ---------------------------------------------------------------------------
#define ATTN_SMEM 49152

__global__ __launch_bounds__(256, 2) void attn_mma()
{
    extern __shared__ char smc[];
    const uint32_t sb = smem_u32(smc);
    const uint32_t QS = sb;

    const int q0 = blockIdx.x * 128;
    const int h  = blockIdx.y;
    const int n  = blockIdx.z;
    const int tid = threadIdx.x;
    const int w = tid >> 5, L = tid & 31;

    const size_t head = (size_t)(n * NH + h) * SEQL * 64;
    const __half* qp = g_q + head;
    const __half* kp = g_k + head;
    const __half* vp = g_v + head;

    for (int c = tid; c < 1024; c += 256) {
        int r = c >> 3, cb = (c & 7) * 16;
        CPA16(QS + SWZ(r * 128 + cb), (const char*)(qp + (size_t)(q0 + r) * 64) + cb);
    }
    {
        uint32_t B = sb + 16384;
        for (int c = tid; c < 512; c += 256) {
            int r = c >> 3, cb = (c & 7) * 16;
            uint32_t off = SWZ(r * 128 + cb);
            size_t go = (size_t)r * 64;
            CPA16(B + off,        (const char*)(kp + go) + cb);
            CPA16(B + 8192 + off, (const char*)(vp + go) + cb);
        }
    }
    CPC();

    float o[8][4] = {};
    float lacc[4] = {};
    uint32_t aq[4][4];
    const uint32_t ones_b[2] = { 0x3C003C00u, 0x3C003C00u };

    const int lr = (L & 7) + ((L >> 3) & 1) * 8;
    const int lc = ((L >> 4) & 1) * 16;
    const int brr = ((L >> 4) & 1) * 8 + (L & 7);
    const int bcc = ((L >> 3) & 1) * 16;
    const int t4 = L >> 2, t2 = (L & 3) * 2;
    const int qa = q0 + w * 16 + t4, qb = qa + 8;

    const unsigned* mrow_a = g_mb + ((size_t)(n * SEQL + qa)) * 32;
    const unsigned* mrow_b = g_mb + ((size_t)(n * SEQL + qb)) * 32;

    for (int kt = 0; kt < 16; kt++) {
        if (kt < 15) {
            uint32_t B = sb + 16384 + ((kt + 1) & 1) * 16384;
            const int k0 = (kt + 1) * 64;
            for (int c = tid; c < 512; c += 256) {
                int r = c >> 3, cb = (c & 7) * 16;
                uint32_t off = SWZ(r * 128 + cb);
                size_t go = (size_t)(k0 + r) * 64;
                CPA16(B + off,        (const char*)(kp + go) + cb);
                CPA16(B + 8192 + off, (const char*)(vp + go) + cb);
            }
            CPC();
            CPW1();
        } else {
            CPW0();
        }
        __syncthreads();

        // prefetch mask words: LDG latency overlaps the S-MMA block below
        unsigned wa0 = mrow_a[kt * 2], wa1 = mrow_a[kt * 2 + 1];
        unsigned wb0 = mrow_b[kt * 2], wb1 = mrow_b[kt * 2 + 1];

        if (kt == 0) {
            #pragma unroll
            for (int ks = 0; ks < 4; ks++)
                ldsm4(aq[ks], QS + SWZ((w * 16 + lr) * 128 + ks * 32 + lc));
        }

        const uint32_t KB = sb + 16384 + (kt & 1) * 16384;
        const uint32_t VB = KB + 8192;

        // S = Q K^T  (already log2-scaled)
        float s[8][4] = {};
        #pragma unroll
        for (int ks = 0; ks < 4; ks++) {
            #pragma unroll
            for (int p = 0; p < 4; p++) {
                uint32_t bh[4];
                ldsm4(bh, KB + SWZ((p * 16 + brr) * 128 + ks * 32 + bcc));
                mma16816(s[2*p],   aq[ks], &bh[0]);
                mma16816(s[2*p+1], aq[ks], &bh[2]);
            }
        }

        // mask-select -> pack -> ex2 (straight-line; no l scalar pipeline)
        uint32_t preg[8][2];
        #pragma unroll
        for (int f = 0; f < 8; f++) {
            unsigned wA = (f < 4) ? wa0 : wa1;
            unsigned wB = (f < 4) ? wb0 : wb1;
            int bit = (f & 3) * 8 + t2;
            float xa0 = ((wA >> bit) & 1)       ? s[f][0] : -100.f;
            float xa1 = ((wA >> (bit + 1)) & 1) ? s[f][1] : -100.f;
            float xb0 = ((wB >> bit) & 1)       ? s[f][2] : -100.f;
            float xb1 = ((wB >> (bit + 1)) & 1) ? s[f][3] : -100.f;
            preg[f][0] = h2ex2(packh2(xa0, xa1));
            preg[f][1] = h2ex2(packh2(xb0, xb1));
        }

        // O += P V ; l += P @ ones
        #pragma unroll
        for (int ks = 0; ks < 4; ks++) {
            uint32_t ph[4] = { preg[2*ks][0], preg[2*ks][1],
                               preg[2*ks+1][0], preg[2*ks+1][1] };
            mma16816(lacc, ph, ones_b);
            #pragma unroll
            for (int p = 0; p < 4; p++) {
                uint32_t bh[4];
                ldsm4t(bh, VB + SWZ((ks * 16 + lr) * 128 + p * 32 + lc));
                mma16816(o[2*p],   ph, &bh[0]);
                mma16816(o[2*p+1], ph, &bh[2]);
            }
        }
        __syncthreads();
    }

    // epilogue: l complete per row; normalize, store
    float ia = 1.0f / lacc[0], ib = 1.0f / lacc[2];
    size_t ba = ((size_t)(n * SEQL + qa)) * EMB + h * 64;
    size_t bb = ((size_t)(n * SEQL + qb)) * EMB + h * 64;
    #pragma unroll
    for (int f = 0; f < 8; f++) {
        int col = f * 8 + t2;
        *reinterpret_cast<uint32_t*>(g_ao + ba + col) = packh2(o[f][0] * ia, o[f][1] * ia);
        *reinterpret_cast<uint32_t*>(g_ao + bb + col) = packh2(o[f][2] * ib, o[f][3] * ib);
    }
}

// ---------------------------------------------------------------------------
// Output projection: (8192 x 1024) @ (1024 x 1024)^T + bias, pure fp16 1-term.
// Tile 256m x 128n, 512 threads (16 warps x 16 rows), K chunks of 64,
// cp.async double-buffered. smem per stage: A 32K | B 16K = 48K; x2 = 96K.
// B tile amortized over 2x rows vs 128x128 (staged traffic 268 -> 196 MB).
// ---------------------------------------------------------------------------
#define OUT_SMEM 98304

__global__ __launch_bounds__(512, 1) void outproj_mma(
    const float* __restrict__ bo, float* __restrict__ out)
{
    extern __shared__ char smc[];
    const uint32_t sb = smem_u32(smc);

    const int m0 = blockIdx.x * 256;
    const int e0 = blockIdx.y * 128;
    const int tid = threadIdx.x;
    const int w = tid >> 5, L = tid & 31;

    // prologue: chunk 0  (A: 256 rows, B: 128 rows)
    {
        uint32_t B = sb;
        for (int c = tid; c < 2048; c += 512) {
            int r = c >> 3, cb = (c & 7) * 16;
            CPA16(B + SWZ(r * 128 + cb), (const char*)(g_ao + (size_t)(m0 + r) * EMB) + cb);
        }
        for (int c = tid; c < 1024; c += 512) {
            int r = c >> 3, cb = (c & 7) * 16;
            CPA16(B + 32768 + SWZ(r * 128 + cb), (const char*)(g_wo + (size_t)(e0 + r) * EMB) + cb);
        }
        CPC();
    }

    float acc[16][4] = {};
    const int lr = (L & 7) + ((L >> 3) & 1) * 8;
    const int lc = ((L >> 4) & 1) * 16;
    const int brr = ((L >> 4) & 1) * 8 + (L & 7);
    const int bcc = ((L >> 3) & 1) * 16;

    for (int kt = 0; kt < 16; kt++) {
        if (kt < 15) {
            uint32_t B = sb + ((kt + 1) & 1) * 49152;
            const int k0 = (kt + 1) * 64;
            for (int c = tid; c < 2048; c += 512) {
                int r = c >> 3, cb = (c & 7) * 16;
                CPA16(B + SWZ(r * 128 + cb),
                      (const char*)(g_ao + (size_t)(m0 + r) * EMB + k0) + cb);
            }
            for (int c = tid; c < 1024; c += 512) {
                int r = c >> 3, cb = (c & 7) * 16;
                CPA16(B + 32768 + SWZ(r * 128 + cb),
                      (const char*)(g_wo + (size_t)(e0 + r) * EMB + k0) + cb);
            }
            CPC();
            CPW1();
        } else {
            CPW0();
        }
        __syncthreads();

        const uint32_t AS = sb + (kt & 1) * 49152;
        const uint32_t BS = AS + 32768;

        #pragma unroll
        for (int ks = 0; ks < 4; ks++) {
            uint32_t a[4];
            ldsm4(a, AS + SWZ((w * 16 + lr) * 128 + ks * 32 + lc));
            #pragma unroll
            for (int p = 0; p < 8; p++) {
                uint32_t b[4];
                ldsm4(b, BS + SWZ((p * 16 + brr) * 128 + ks * 32 + bcc));
                mma16816(acc[2*p],   a, &b[0]);
                mma16816(acc[2*p+1], a, &b[2]);
            }
        }
        __syncthreads();
    }

    // epilogue
    const int t4 = L >> 2, t2 = (L & 3) * 2;
    const int r0 = m0 + w * 16 + t4, r1 = r0 + 8;
    #pragma unroll
    for (int f = 0; f < 16; f++) {
        int col = e0 + f * 8 + t2;
        float b0v = bo[col], b1v = bo[col + 1];
        float2 v0 = make_float2(acc[f][0] + b0v, acc[f][1] + b1v);
        float2 v1 = make_float2(acc[f][2] + b0v, acc[f][3] + b1v);
        *reinterpret_cast<float2*>(out + (size_t)r0 * EMB + col) = v0;
        *reinterpret_cast<float2*>(out + (size_t)r1 * EMB + col) = v1;
    }
}

// ---------------------------------------------------------------------------
extern "C" void kernel_launch(void* const* d_in, const int* in_sizes, int n_in,
                              void* d_out, int out_size)
{
    const float* values = (const float*)d_in[0];
    const float* keys   = (const float*)d_in[1];
    const float* query  = (const float*)d_in[2];
    const int*   mask   = (const int*)d_in[3];
    const float* Wv     = (const float*)d_in[4];
    const float* Wk     = (const float*)d_in[5];
    const float* Wq     = (const float*)d_in[6];
    const float* Wo     = (const float*)d_in[7];
    const float* bo     = (const float*)d_in[8];
    float* out = (float*)d_out;
    (void)in_sizes; (void)n_in; (void)out_size;

    cudaFuncSetAttribute(proj_mma,    cudaFuncAttributeMaxDynamicSharedMemorySize, PROJ_SMEM);
    cudaFuncSetAttribute(attn_mma,    cudaFuncAttributeMaxDynamicSharedMemorySize, ATTN_SMEM);
    cudaFuncSetAttribute(outproj_mma, cudaFuncAttributeMaxDynamicSharedMemorySize, OUT_SMEM);

    pack_mask<<<NB*SEQL*SEQL/1024, 256>>>(mask);
    conv_wo<<<EMB*EMB/1024, 256>>>(Wo);
    proj_mma<<<dim3(1024, 3), 256, PROJ_SMEM>>>(values, keys, query, Wv, Wk, Wq);
    attn_mma<<<dim3(SEQL/128, NH, NB), 256, ATTN_SMEM>>>();
    outproj_mma<<<dim3(32, 8), 512, OUT_SMEM>>>(bo, out);
}

// round 12
// speedup vs baseline: 1.4880x; 1.0867x over previous
#include <cuda_runtime.h>
#include <cuda_fp16.h>
#include <cstdint>
#include <float.h>

#define NB   8
#define SEQL 1024
#define NH   16
#define HD   64
#define EMB  1024

// ---------------------------------------------------------------------------
// Device scratch (allocation-free rule)
// ---------------------------------------------------------------------------
__device__ __half g_q [NB*NH*SEQL*HD];     // projected Q (fp16, pre-scaled by XSCALE)
__device__ __half g_k [NB*NH*SEQL*HD];     // projected K (fp16)
__device__ __half g_v [NB*NH*SEQL*HD];     // projected V (fp16)
__device__ __half g_ao[NB*SEQL*EMB];       // attention out (fp16) [n][l][e]
__device__ __half g_wo[EMB*EMB];           // Wo fp16
__device__ unsigned g_mb[NB*SEQL*SEQL/32]; // packed mask bits

// log2 domain: softmax(z/32) = exp2(z * C) / sum, C = log2(e)/32, folded into Wq.
#define XSCALE 0.0450842139f          /* 0.03125 * log2(e) */

// ---------------------------------------------------------------------------
// helpers
// ---------------------------------------------------------------------------
__device__ __forceinline__ uint32_t smem_u32(const void* p) {
    uint32_t a;
    asm("{ .reg .u64 t; cvta.to.shared.u64 t, %1; cvt.u32.u64 %0, t; }"
        : "=r"(a) : "l"(p));
    return a;
}

#define SWZ(o) ((o) ^ ((((uint32_t)(o)) >> 3) & 0x70u))

__device__ __forceinline__ void ldsm4(uint32_t r[4], uint32_t a) {
    asm volatile("ldmatrix.sync.aligned.m8n8.x4.shared.b16 {%0,%1,%2,%3}, [%4];"
        : "=r"(r[0]), "=r"(r[1]), "=r"(r[2]), "=r"(r[3]) : "r"(a));
}
__device__ __forceinline__ void ldsm4t(uint32_t r[4], uint32_t a) {
    asm volatile("ldmatrix.sync.aligned.m8n8.x4.trans.shared.b16 {%0,%1,%2,%3}, [%4];"
        : "=r"(r[0]), "=r"(r[1]), "=r"(r[2]), "=r"(r[3]) : "r"(a));
}
__device__ __forceinline__ void mma16816(float* c, const uint32_t* a, const uint32_t* b) {
    asm volatile("mma.sync.aligned.m16n8k16.row.col.f32.f16.f16.f32 "
        "{%0,%1,%2,%3}, {%4,%5,%6,%7}, {%8,%9}, {%0,%1,%2,%3};"
        : "+f"(c[0]), "+f"(c[1]), "+f"(c[2]), "+f"(c[3])
        : "r"(a[0]), "r"(a[1]), "r"(a[2]), "r"(a[3]), "r"(b[0]), "r"(b[1]));
}
__device__ __forceinline__ uint32_t h2ex2(uint32_t x) {
    uint32_t r;
    asm("ex2.approx.f16x2 %0, %1;" : "=r"(r) : "r"(x));
    return r;
}
__device__ __forceinline__ uint32_t packh2(float a, float b) {
    __half2 h = __floats2half2_rn(a, b);
    return *reinterpret_cast<uint32_t*>(&h);
}

#define CPA16(dst, src) \
    asm volatile("cp.async.cg.shared.global [%0], [%1], 16;" \
        :: "r"((uint32_t)(dst)), "l"((const void*)(src)) : "memory")
#define CPC()  asm volatile("cp.async.commit_group;" ::: "memory")
#define CPW0() asm volatile("cp.async.wait_group 0;" ::: "memory")
#define CPW1() asm volatile("cp.async.wait_group 1;" ::: "memory")

// ---------------------------------------------------------------------------
// Fused front kernel: grid (1024, 5), 256 threads.
//   y = 0..2 : QKV projection (pure fp16 MMA), which = y
//   y = 3    : mask bit-packing (8 chunks per block)
//   y = 4    : Wo fp32 -> fp16 conversion
// All three roles are mutually independent; fusing removes the serial
// small-kernel time ahead of proj.
// smem (proj role): A 16K | W 8K = 24K
// ---------------------------------------------------------------------------
#define FRONT_SMEM 24576

__global__ __launch_bounds__(256) void front_kernel(
    const float* __restrict__ vin, const float* __restrict__ kin,
    const float* __restrict__ qin,
    const float* __restrict__ Wv, const float* __restrict__ Wk,
    const float* __restrict__ Wq,
    const int* __restrict__ mask, const float* __restrict__ wo)
{
    const int role = blockIdx.y;
    const int tid = threadIdx.x;

    if (role == 3) {
        // pack_mask: 1024 blocks x 256 threads x 8 iterations x 4 ints
        #pragma unroll
        for (int it = 0; it < 8; it++) {
            size_t base = (((size_t)blockIdx.x * 8 + it) * 256 + tid) * 4;
            int4 v = *reinterpret_cast<const int4*>(mask + base);
            uint32_t nib = (uint32_t)(v.x != 0) | ((uint32_t)(v.y != 0) << 1)
                         | ((uint32_t)(v.z != 0) << 2) | ((uint32_t)(v.w != 0) << 3);
            nib |= __shfl_xor_sync(0xffffffffu, nib, 1) << 4;
            nib |= __shfl_xor_sync(0xffffffffu, nib, 2) << 8;
            nib |= __shfl_xor_sync(0xffffffffu, nib, 4) << 16;
            if ((tid & 7) == 0) g_mb[base >> 5] = nib;
        }
        return;
    }
    if (role == 4) {
        // conv_wo: 1024 blocks x 256 threads x 4 floats
        size_t i = ((size_t)blockIdx.x * 256 + tid) * 4;
        float4 f = *reinterpret_cast<const float4*>(wo + i);
        uint32_t u0 = packh2(f.x, f.y), u1 = packh2(f.z, f.w);
        *reinterpret_cast<uint2*>(g_wo + i) = make_uint2(u0, u1);
        return;
    }

    // ---- proj role (which = role 0..2) ----
    extern __shared__ char smc[];
    const uint32_t sb = smem_u32(smc);
    const uint32_t AS = sb, WS = sb + 16384;

    const int which = role;
    const float* in = (which == 0) ? vin : (which == 1) ? kin : qin;
    const float* W  = (which == 0) ? Wv  : (which == 1) ? Wk  : Wq;
    __half* outp    = (which == 0) ? g_v : (which == 1) ? g_k : g_q;
    const float wscale = (which == 2) ? XSCALE : 1.0f;

    const int m0 = blockIdx.x * 128;
    const int w = tid >> 5, L = tid & 31;

    for (int c = tid; c < 1024; c += 256) {
        int r = c >> 3, c0 = (c & 7) * 8;
        const float4* s = reinterpret_cast<const float4*>(in + (size_t)(m0 + r) * 64 + c0);
        float4 f0 = s[0], f1 = s[1];
        uint32_t u0 = packh2(f0.x, f0.y), u1 = packh2(f0.z, f0.w);
        uint32_t u2 = packh2(f1.x, f1.y), u3 = packh2(f1.z, f1.w);
        *reinterpret_cast<uint4*>(smc + SWZ(r * 128 + c0 * 2)) = make_uint4(u0, u1, u2, u3);
    }
    for (int c = tid; c < 512; c += 256) {
        int r = c >> 3, c0 = (c & 7) * 8;
        const float4* s = reinterpret_cast<const float4*>(W + (size_t)r * 64 + c0);
        float4 f0 = s[0], f1 = s[1];
        uint32_t u0 = packh2(f0.x * wscale, f0.y * wscale);
        uint32_t u1 = packh2(f0.z * wscale, f0.w * wscale);
        uint32_t u2 = packh2(f1.x * wscale, f1.y * wscale);
        uint32_t u3 = packh2(f1.z * wscale, f1.w * wscale);
        *reinterpret_cast<uint4*>(smc + 16384 + SWZ(r * 128 + c0 * 2)) = make_uint4(u0, u1, u2, u3);
    }
    __syncthreads();

    float acc[8][4] = {};
    const int lr = (L & 7) + ((L >> 3) & 1) * 8;
    const int lc = ((L >> 4) & 1) * 16;
    const int br = ((L >> 4) & 1) * 8 + (L & 7);
    const int bc = ((L >> 3) & 1) * 16;

    #pragma unroll
    for (int ks = 0; ks < 4; ks++) {
        uint32_t a[4];
        ldsm4(a, AS + SWZ((w * 16 + lr) * 128 + ks * 32 + lc));
        #pragma unroll
        for (int p = 0; p < 4; p++) {
            uint32_t b[4];
            ldsm4(b, WS + SWZ((p * 16 + br) * 128 + ks * 32 + bc));
            mma16816(acc[2*p],   a, &b[0]);
            mma16816(acc[2*p+1], a, &b[2]);
        }
    }

    const int t4 = L >> 2, t2 = (L & 3) * 2;
    const int r0 = m0 + w * 16 + t4, r1 = r0 + 8;
    size_t b0, b1;
    {
        int h0i = r0 & 15, l0i = (r0 >> 4) & 1023, n0i = r0 >> 14;
        int h1i = r1 & 15, l1i = (r1 >> 4) & 1023, n1i = r1 >> 14;
        b0 = ((size_t)((n0i * 16 + h0i) * 1024 + l0i)) * 64;
        b1 = ((size_t)((n1i * 16 + h1i) * 1024 + l1i)) * 64;
    }
    #pragma unroll
    for (int f = 0; f < 8; f++) {
        int col = f * 8 + t2;
        *reinterpret_cast<uint32_t*>(outp + b0 + col) = packh2(acc[f][0], acc[f][1]);
        *reinterpret_cast<uint32_t*>(outp + b1 + col) = packh2(acc[f][2], acc[f][3]);
    }
}

// ---------------------------------------------------------------------------
// Flash attention (exact R9 structure — 118.9us known-good): block = (128 q
// rows, head, batch); 8 warps x 16 rows. K-tiles of 64, cp.async double-
// buffered. No-max log2 softmax; l = P @ ones via extra n=8 MMA.
// smem: Q 16K | buf0 {K 8K, V 8K} | buf1 {...} = 48K
// ---------------------------------------------------------------------------
#define ATTN_SMEM 49152

__global__ __launch_bounds__(256, 2) void attn_mma()
{
    extern __shared__ char smc[];
    const uint32_t sb = smem_u32(smc);
    const uint32_t QS = sb;

    const int q0 = blockIdx.x * 128;
    const int h  = blockIdx.y;
    const int n  = blockIdx.z;
    const int tid = threadIdx.x;
    const int w = tid >> 5, L = tid & 31;

    const size_t head = (size_t)(n * NH + h) * SEQL * 64;
    const __half* qp = g_q + head;
    const __half* kp = g_k + head;
    const __half* vp = g_v + head;

    for (int c = tid; c < 1024; c += 256) {
        int r = c >> 3, cb = (c & 7) * 16;
        CPA16(QS + SWZ(r * 128 + cb), (const char*)(qp + (size_t)(q0 + r) * 64) + cb);
    }
    {
        uint32_t B = sb + 16384;
        for (int c = tid; c < 512; c += 256) {
            int r = c >> 3, cb = (c & 7) * 16;
            uint32_t off = SWZ(r * 128 + cb);
            size_t go = (size_t)r * 64;
            CPA16(B + off,        (const char*)(kp + go) + cb);
            CPA16(B + 8192 + off, (const char*)(vp + go) + cb);
        }
    }
    CPC();

    float o[8][4] = {};
    float lacc[4] = {};
    uint32_t aq[4][4];
    const uint32_t ones_b[2] = { 0x3C003C00u, 0x3C003C00u };

    const int lr = (L & 7) + ((L >> 3) & 1) * 8;
    const int lc = ((L >> 4) & 1) * 16;
    const int brr = ((L >> 4) & 1) * 8 + (L & 7);
    const int bcc = ((L >> 3) & 1) * 16;
    const int t4 = L >> 2, t2 = (L & 3) * 2;
    const int qa = q0 + w * 16 + t4, qb = qa + 8;

    const unsigned* mrow_a = g_mb + ((size_t)(n * SEQL + qa)) * 32;
    const unsigned* mrow_b = g_mb + ((size_t)(n * SEQL + qb)) * 32;

    for (int kt = 0; kt < 16; kt++) {
        if (kt < 15) {
            uint32_t B = sb + 16384 + ((kt + 1) & 1) * 16384;
            const int k0 = (kt + 1) * 64;
            for (int c = tid; c < 512; c += 256) {
                int r = c >> 3, cb = (c & 7) * 16;
                uint32_t off = SWZ(r * 128 + cb);
                size_t go = (size_t)(k0 + r) * 64;
                CPA16(B + off,        (const char*)(kp + go) + cb);
                CPA16(B + 8192 + off, (const char*)(vp + go) + cb);
            }
            CPC();
            CPW1();
        } else {
            CPW0();
        }
        __syncthreads();

        // prefetch mask words: LDG latency overlaps the S-MMA block below
        unsigned wa0 = mrow_a[kt * 2], wa1 = mrow_a[kt * 2 + 1];
        unsigned wb0 = mrow_b[kt * 2], wb1 = mrow_b[kt * 2 + 1];

        if (kt == 0) {
            #pragma unroll
            for (int ks = 0; ks < 4; ks++)
                ldsm4(aq[ks], QS + SWZ((w * 16 + lr) * 128 + ks * 32 + lc));
        }

        const uint32_t KB = sb + 16384 + (kt & 1) * 16384;
        const uint32_t VB = KB + 8192;

        // S = Q K^T  (already log2-scaled)
        float s[8][4] = {};
        #pragma unroll
        for (int ks = 0; ks < 4; ks++) {
            #pragma unroll
            for (int p = 0; p < 4; p++) {
                uint32_t bh[4];
                ldsm4(bh, KB + SWZ((p * 16 + brr) * 128 + ks * 32 + bcc));
                mma16816(s[2*p],   aq[ks], &bh[0]);
                mma16816(s[2*p+1], aq[ks], &bh[2]);
            }
        }

        // mask-select -> pack -> ex2 (straight-line; no l scalar pipeline)
        uint32_t preg[8][2];
        #pragma unroll
        for (int f = 0; f < 8; f++) {
            unsigned wA = (f < 4) ? wa0 : wa1;
            unsigned wB = (f < 4) ? wb0 : wb1;
            int bit = (f & 3) * 8 + t2;
            float xa0 = ((wA >> bit) & 1)       ? s[f][0] : -100.f;
            float xa1 = ((wA >> (bit + 1)) & 1) ? s[f][1] : -100.f;
            float xb0 = ((wB >> bit) & 1)       ? s[f][2] : -100.f;
            float xb1 = ((wB >> (bit + 1)) & 1) ? s[f][3] : -100.f;
            preg[f][0] = h2ex2(packh2(xa0, xa1));
            preg[f][1] = h2ex2(packh2(xb0, xb1));
        }

        // O += P V ; l += P @ ones
        #pragma unroll
        for (int ks = 0; ks < 4; ks++) {
            uint32_t ph[4] = { preg[2*ks][0], preg[2*ks][1],
                               preg[2*ks+1][0], preg[2*ks+1][1] };
            mma16816(lacc, ph, ones_b);
            #pragma unroll
            for (int p = 0; p < 4; p++) {
                uint32_t bh[4];
                ldsm4t(bh, VB + SWZ((ks * 16 + lr) * 128 + p * 32 + lc));
                mma16816(o[2*p],   ph, &bh[0]);
                mma16816(o[2*p+1], ph, &bh[2]);
            }
        }
        __syncthreads();
    }

    // epilogue: l complete per row; normalize, store
    float ia = 1.0f / lacc[0], ib = 1.0f / lacc[2];
    size_t ba = ((size_t)(n * SEQL + qa)) * EMB + h * 64;
    size_t bb = ((size_t)(n * SEQL + qb)) * EMB + h * 64;
    #pragma unroll
    for (int f = 0; f < 8; f++) {
        int col = f * 8 + t2;
        *reinterpret_cast<uint32_t*>(g_ao + ba + col) = packh2(o[f][0] * ia, o[f][1] * ia);
        *reinterpret_cast<uint32_t*>(g_ao + bb + col) = packh2(o[f][2] * ib, o[f][3] * ib);
    }
}

// ---------------------------------------------------------------------------
// Output projection (exact R9 structure — known-good): (8192 x 1024) @
// (1024 x 1024)^T + bias, pure fp16 1-term. Tile 128x128, 256 threads,
// K chunks of 64, cp.async double-buffered, 2 CTAs/SM.
// smem per stage: A 16K | B 16K = 32K; x2 = 64K
// ---------------------------------------------------------------------------
#define OUT_SMEM 65536

__global__ __launch_bounds__(256, 2) void outproj_mma(
    const float* __restrict__ bo, float* __restrict__ out)
{
    extern __shared__ char smc[];
    const uint32_t sb = smem_u32(smc);

    const int m0 = blockIdx.x * 128;
    const int e0 = blockIdx.y * 128;
    const int tid = threadIdx.x;
    const int w = tid >> 5, L = tid & 31;

    {
        uint32_t B = sb;
        for (int c = tid; c < 1024; c += 256) {
            int r = c >> 3, cb = (c & 7) * 16;
            uint32_t off = SWZ(r * 128 + cb);
            CPA16(B + off,         (const char*)(g_ao + (size_t)(m0 + r) * EMB) + cb);
            CPA16(B + 16384 + off, (const char*)(g_wo + (size_t)(e0 + r) * EMB) + cb);
        }
        CPC();
    }

    float acc[16][4] = {};
    const int lr = (L & 7) + ((L >> 3) & 1) * 8;
    const int lc = ((L >> 4) & 1) * 16;
    const int brr = ((L >> 4) & 1) * 8 + (L & 7);
    const int bcc = ((L >> 3) & 1) * 16;

    for (int kt = 0; kt < 16; kt++) {
        if (kt < 15) {
            uint32_t B = sb + ((kt + 1) & 1) * 32768;
            const int k0 = (kt + 1) * 64;
            for (int c = tid; c < 1024; c += 256) {
                int r = c >> 3, cb = (c & 7) * 16;
                uint32_t off = SWZ(r * 128 + cb);
                CPA16(B + off,         (const char*)(g_ao + (size_t)(m0 + r) * EMB + k0) + cb);
                CPA16(B + 16384 + off, (const char*)(g_wo + (size_t)(e0 + r) * EMB + k0) + cb);
            }
            CPC();
            CPW1();
        } else {
            CPW0();
        }
        __syncthreads();

        const uint32_t AS = sb + (kt & 1) * 32768;
        const uint32_t BS = AS + 16384;

        #pragma unroll
        for (int ks = 0; ks < 4; ks++) {
            uint32_t a[4];
            ldsm4(a, AS + SWZ((w * 16 + lr) * 128 + ks * 32 + lc));
            #pragma unroll
            for (int p = 0; p < 8; p++) {
                uint32_t b[4];
                ldsm4(b, BS + SWZ((p * 16 + brr) * 128 + ks * 32 + bcc));
                mma16816(acc[2*p],   a, &b[0]);
                mma16816(acc[2*p+1], a, &b[2]);
            }
        }
        __syncthreads();
    }

    const int t4 = L >> 2, t2 = (L & 3) * 2;
    const int r0 = m0 + w * 16 + t4, r1 = r0 + 8;
    #pragma unroll
    for (int f = 0; f < 16; f++) {
        int col = e0 + f * 8 + t2;
        float b0v = bo[col], b1v = bo[col + 1];
        float2 v0 = make_float2(acc[f][0] + b0v, acc[f][1] + b1v);
        float2 v1 = make_float2(acc[f][2] + b0v, acc[f][3] + b1v);
        *reinterpret_cast<float2*>(out + (size_t)r0 * EMB + col) = v0;
        *reinterpret_cast<float2*>(out + (size_t)r1 * EMB + col) = v1;
    }
}

// ---------------------------------------------------------------------------
extern "C" void kernel_launch(void* const* d_in, const int* in_sizes, int n_in,
                              void* d_out, int out_size)
{
    const float* values = (const float*)d_in[0];
    const float* keys   = (const float*)d_in[1];
    const float* query  = (const float*)d_in[2];
    const int*   mask   = (const int*)d_in[3];
    const float* Wv     = (const float*)d_in[4];
    const float* Wk     = (const float*)d_in[5];
    const float* Wq     = (const float*)d_in[6];
    const float* Wo     = (const float*)d_in[7];
    const float* bo     = (const float*)d_in[8];
    float* out = (float*)d_out;
    (void)in_sizes; (void)n_in; (void)out_size;

    cudaFuncSetAttribute(front_kernel, cudaFuncAttributeMaxDynamicSharedMemorySize, FRONT_SMEM);
    cudaFuncSetAttribute(attn_mma,     cudaFuncAttributeMaxDynamicSharedMemorySize, ATTN_SMEM);
    cudaFuncSetAttribute(outproj_mma,  cudaFuncAttributeMaxDynamicSharedMemorySize, OUT_SMEM);

    front_kernel<<<dim3(1024, 5), 256, FRONT_SMEM>>>(values, keys, query,
                                                     Wv, Wk, Wq, mask, Wo);
    attn_mma<<<dim3(SEQL/128, NH, NB), 256, ATTN_SMEM>>>();
    outproj_mma<<<dim3(64, 8), 256, OUT_SMEM>>>(bo, out);
}

// round 13
// speedup vs baseline: 1.5134x; 1.0171x over previous
#include <cuda_runtime.h>
#include <cuda_fp16.h>
#include <cstdint>
#include <float.h>

#define NB   8
#define SEQL 1024
#define NH   16
#define HD   64
#define EMB  1024

// ---------------------------------------------------------------------------
// Device scratch (allocation-free rule)
// ---------------------------------------------------------------------------
__device__ __half g_q [NB*NH*SEQL*HD];     // projected Q (fp16, pre-scaled by XSCALE)
__device__ __half g_k [NB*NH*SEQL*HD];     // projected K (fp16)
__device__ __half g_v [NB*NH*SEQL*HD];     // projected V (fp16)
__device__ __half g_ao[NB*SEQL*EMB];       // attention out (fp16) [n][l][e]
__device__ __half g_wo[EMB*EMB];           // Wo fp16
__device__ unsigned g_mb[NB*SEQL*SEQL/32]; // packed mask bits

// log2 domain: softmax(z/32) = exp2(z * C) / sum, C = log2(e)/32, folded into Wq.
#define XSCALE 0.0450842139f          /* 0.03125 * log2(e) */

// ---------------------------------------------------------------------------
// helpers
// ---------------------------------------------------------------------------
__device__ __forceinline__ uint32_t smem_u32(const void* p) {
    uint32_t a;
    asm("{ .reg .u64 t; cvta.to.shared.u64 t, %1; cvt.u32.u64 %0, t; }"
        : "=r"(a) : "l"(p));
    return a;
}

#define SWZ(o) ((o) ^ ((((uint32_t)(o)) >> 3) & 0x70u))

__device__ __forceinline__ void ldsm4(uint32_t r[4], uint32_t a) {
    asm volatile("ldmatrix.sync.aligned.m8n8.x4.shared.b16 {%0,%1,%2,%3}, [%4];"
        : "=r"(r[0]), "=r"(r[1]), "=r"(r[2]), "=r"(r[3]) : "r"(a));
}
__device__ __forceinline__ void ldsm4t(uint32_t r[4], uint32_t a) {
    asm volatile("ldmatrix.sync.aligned.m8n8.x4.trans.shared.b16 {%0,%1,%2,%3}, [%4];"
        : "=r"(r[0]), "=r"(r[1]), "=r"(r[2]), "=r"(r[3]) : "r"(a));
}
__device__ __forceinline__ void mma16816(float* c, const uint32_t* a, const uint32_t* b) {
    asm volatile("mma.sync.aligned.m16n8k16.row.col.f32.f16.f16.f32 "
        "{%0,%1,%2,%3}, {%4,%5,%6,%7}, {%8,%9}, {%0,%1,%2,%3};"
        : "+f"(c[0]), "+f"(c[1]), "+f"(c[2]), "+f"(c[3])
        : "r"(a[0]), "r"(a[1]), "r"(a[2]), "r"(a[3]), "r"(b[0]), "r"(b[1]));
}
__device__ __forceinline__ uint32_t h2ex2(uint32_t x) {
    uint32_t r;
    asm("ex2.approx.f16x2 %0, %1;" : "=r"(r) : "r"(x));
    return r;
}
__device__ __forceinline__ uint32_t packh2(float a, float b) {
    __half2 h = __floats2half2_rn(a, b);
    return *reinterpret_cast<uint32_t*>(&h);
}

#define CPA16(dst, src) \
    asm volatile("cp.async.cg.shared.global [%0], [%1], 16;" \
        :: "r"((uint32_t)(dst)), "l"((const void*)(src)) : "memory")
#define CPC()  asm volatile("cp.async.commit_group;" ::: "memory")
#define CPW0() asm volatile("cp.async.wait_group 0;" ::: "memory")
#define CPW1() asm volatile("cp.async.wait_group 1;" ::: "memory")

// ---------------------------------------------------------------------------
// Fused front kernel: grid (1024, 5), 256 threads.
//   y = 0..2 : QKV projection (pure fp16 MMA), which = y
//   y = 3    : mask bit-packing (8 chunks per block)
//   y = 4    : Wo fp32 -> fp16 conversion
// Proj epilogue stages results through smem for coalesced STG.128 output.
// smem (proj role): A 16K | W 8K = 24K
// ---------------------------------------------------------------------------
#define FRONT_SMEM 24576

__global__ __launch_bounds__(256) void front_kernel(
    const float* __restrict__ vin, const float* __restrict__ kin,
    const float* __restrict__ qin,
    const float* __restrict__ Wv, const float* __restrict__ Wk,
    const float* __restrict__ Wq,
    const int* __restrict__ mask, const float* __restrict__ wo)
{
    const int role = blockIdx.y;
    const int tid = threadIdx.x;

    if (role == 3) {
        #pragma unroll
        for (int it = 0; it < 8; it++) {
            size_t base = (((size_t)blockIdx.x * 8 + it) * 256 + tid) * 4;
            int4 v = *reinterpret_cast<const int4*>(mask + base);
            uint32_t nib = (uint32_t)(v.x != 0) | ((uint32_t)(v.y != 0) << 1)
                         | ((uint32_t)(v.z != 0) << 2) | ((uint32_t)(v.w != 0) << 3);
            nib |= __shfl_xor_sync(0xffffffffu, nib, 1) << 4;
            nib |= __shfl_xor_sync(0xffffffffu, nib, 2) << 8;
            nib |= __shfl_xor_sync(0xffffffffu, nib, 4) << 16;
            if ((tid & 7) == 0) g_mb[base >> 5] = nib;
        }
        return;
    }
    if (role == 4) {
        size_t i = ((size_t)blockIdx.x * 256 + tid) * 4;
        float4 f = *reinterpret_cast<const float4*>(wo + i);
        uint32_t u0 = packh2(f.x, f.y), u1 = packh2(f.z, f.w);
        *reinterpret_cast<uint2*>(g_wo + i) = make_uint2(u0, u1);
        return;
    }

    // ---- proj role (which = role 0..2) ----
    extern __shared__ char smc[];
    const uint32_t sb = smem_u32(smc);
    const uint32_t AS = sb, WS = sb + 16384;

    const int which = role;
    const float* in = (which == 0) ? vin : (which == 1) ? kin : qin;
    const float* W  = (which == 0) ? Wv  : (which == 1) ? Wk  : Wq;
    __half* outp    = (which == 0) ? g_v : (which == 1) ? g_k : g_q;
    const float wscale = (which == 2) ? XSCALE : 1.0f;

    const int m0 = blockIdx.x * 128;
    const int w = tid >> 5, L = tid & 31;

    for (int c = tid; c < 1024; c += 256) {
        int r = c >> 3, c0 = (c & 7) * 8;
        const float4* s = reinterpret_cast<const float4*>(in + (size_t)(m0 + r) * 64 + c0);
        float4 f0 = s[0], f1 = s[1];
        uint32_t u0 = packh2(f0.x, f0.y), u1 = packh2(f0.z, f0.w);
        uint32_t u2 = packh2(f1.x, f1.y), u3 = packh2(f1.z, f1.w);
        *reinterpret_cast<uint4*>(smc + SWZ(r * 128 + c0 * 2)) = make_uint4(u0, u1, u2, u3);
    }
    for (int c = tid; c < 512; c += 256) {
        int r = c >> 3, c0 = (c & 7) * 8;
        const float4* s = reinterpret_cast<const float4*>(W + (size_t)r * 64 + c0);
        float4 f0 = s[0], f1 = s[1];
        uint32_t u0 = packh2(f0.x * wscale, f0.y * wscale);
        uint32_t u1 = packh2(f0.z * wscale, f0.w * wscale);
        uint32_t u2 = packh2(f1.x * wscale, f1.y * wscale);
        uint32_t u3 = packh2(f1.z * wscale, f1.w * wscale);
        *reinterpret_cast<uint4*>(smc + 16384 + SWZ(r * 128 + c0 * 2)) = make_uint4(u0, u1, u2, u3);
    }
    __syncthreads();

    float acc[8][4] = {};
    const int lr = (L & 7) + ((L >> 3) & 1) * 8;
    const int lc = ((L >> 4) & 1) * 16;
    const int br = ((L >> 4) & 1) * 8 + (L & 7);
    const int bc = ((L >> 3) & 1) * 16;

    #pragma unroll
    for (int ks = 0; ks < 4; ks++) {
        uint32_t a[4];
        ldsm4(a, AS + SWZ((w * 16 + lr) * 128 + ks * 32 + lc));
        #pragma unroll
        for (int p = 0; p < 4; p++) {
            uint32_t b[4];
            ldsm4(b, WS + SWZ((p * 16 + br) * 128 + ks * 32 + bc));
            mma16816(acc[2*p],   a, &b[0]);
            mma16816(acc[2*p+1], a, &b[2]);
        }
    }

    // epilogue: stage packed fp16 into AS (reuse), then coalesced STG.128
    const int t4 = L >> 2, t2 = (L & 3) * 2;
    __syncthreads();   // all ldsm reads of AS/WS complete
    {
        const int row0 = w * 16 + t4, row1 = row0 + 8;
        #pragma unroll
        for (int f = 0; f < 8; f++) {
            int colb = (f * 8 + t2) * 2;
            uint32_t u0 = packh2(acc[f][0], acc[f][1]);
            uint32_t u1 = packh2(acc[f][2], acc[f][3]);
            *reinterpret_cast<uint32_t*>(smc + SWZ(row0 * 128 + colb)) = u0;
            *reinterpret_cast<uint32_t*>(smc + SWZ(row1 * 128 + colb)) = u1;
        }
    }
    __syncthreads();
    {
        const int rr = tid >> 1, hh = tid & 1;
        const int m = m0 + rr;
        const int hi = m & 15, li = (m >> 4) & 1023, ni = m >> 14;
        size_t base = ((size_t)((ni * 16 + hi) * 1024 + li)) * 64 + hh * 32;
        #pragma unroll
        for (int j = 0; j < 4; j++) {
            uint4 v = *reinterpret_cast<uint4*>(smc + SWZ(rr * 128 + hh * 64 + j * 16));
            *reinterpret_cast<uint4*>(outp + base + j * 8) = v;
        }
    }
}

// ---------------------------------------------------------------------------
// Flash attention: block = (128 q rows, head, batch); 8 warps x 16 rows.
// K-tiles of 64. 3-buffer cp.async ring, ONE barrier per tile (prefetch for
// kt+2 issued AFTER the barrier -> targets buf (kt-1)%3 which all warps have
// finished). MMA/softmax structure identical to R9 (known-good).
// smem: Q 16K | ring 3 x {K 8K, V 8K} = 64K
// ---------------------------------------------------------------------------
#define ATTN_SMEM 65536

__global__ __launch_bounds__(256, 2) void attn_mma()
{
    extern __shared__ char smc[];
    const uint32_t sb = smem_u32(smc);
    const uint32_t QS = sb;
    const uint32_t RING = sb + 16384;

    const int q0 = blockIdx.x * 128;
    const int h  = blockIdx.y;
    const int n  = blockIdx.z;
    const int tid = threadIdx.x;
    const int w = tid >> 5, L = tid & 31;

    const size_t head = (size_t)(n * NH + h) * SEQL * 64;
    const __half* qp = g_q + head;
    const __half* kp = g_k + head;
    const __half* vp = g_v + head;

    // prologue: group0 = Q + tile0 -> buf0; group1 = tile1 -> buf1
    for (int c = tid; c < 1024; c += 256) {
        int r = c >> 3, cb = (c & 7) * 16;
        CPA16(QS + SWZ(r * 128 + cb), (const char*)(qp + (size_t)(q0 + r) * 64) + cb);
    }
    for (int c = tid; c < 512; c += 256) {
        int r = c >> 3, cb = (c & 7) * 16;
        uint32_t off = SWZ(r * 128 + cb);
        size_t go = (size_t)r * 64;
        CPA16(RING + off,        (const char*)(kp + go) + cb);
        CPA16(RING + 8192 + off, (const char*)(vp + go) + cb);
    }
    CPC();
    for (int c = tid; c < 512; c += 256) {
        int r = c >> 3, cb = (c & 7) * 16;
        uint32_t off = SWZ(r * 128 + cb);
        size_t go = (size_t)(64 + r) * 64;
        CPA16(RING + 16384 + off,        (const char*)(kp + go) + cb);
        CPA16(RING + 16384 + 8192 + off, (const char*)(vp + go) + cb);
    }
    CPC();

    float o[8][4] = {};
    float lacc[4] = {};
    uint32_t aq[4][4];
    const uint32_t ones_b[2] = { 0x3C003C00u, 0x3C003C00u };

    const int lr = (L & 7) + ((L >> 3) & 1) * 8;
    const int lc = ((L >> 4) & 1) * 16;
    const int brr = ((L >> 4) & 1) * 8 + (L & 7);
    const int bcc = ((L >> 3) & 1) * 16;
    const int t4 = L >> 2, t2 = (L & 3) * 2;
    const int qa = q0 + w * 16 + t4, qb = qa + 8;

    const unsigned* mrow_a = g_mb + ((size_t)(n * SEQL + qa)) * 32;
    const unsigned* mrow_b = g_mb + ((size_t)(n * SEQL + qb)) * 32;

    int cur = 0, pre = 2;   // kt%3, (kt+2)%3
    for (int kt = 0; kt < 16; kt++) {
        // group kt must be complete (pending: kt, kt+1)
        if (kt < 15) { CPW1(); } else { CPW0(); }
        __syncthreads();   // single barrier: kt data visible AND kt-1 reads done

        // prefetch kt+2 into buf (kt+2)%3 == (kt-1)%3 (safe after barrier)
        if (kt < 14) {
            uint32_t B = RING + pre * 16384;
            const int k0 = (kt + 2) * 64;
            for (int c = tid; c < 512; c += 256) {
                int r = c >> 3, cb = (c & 7) * 16;
                uint32_t off = SWZ(r * 128 + cb);
                size_t go = (size_t)(k0 + r) * 64;
                CPA16(B + off,        (const char*)(kp + go) + cb);
                CPA16(B + 8192 + off, (const char*)(vp + go) + cb);
            }
            CPC();
        }

        // prefetch mask words (LDG overlaps S-MMA block)
        unsigned wa0 = mrow_a[kt * 2], wa1 = mrow_a[kt * 2 + 1];
        unsigned wb0 = mrow_b[kt * 2], wb1 = mrow_b[kt * 2 + 1];

        if (kt == 0) {
            #pragma unroll
            for (int ks = 0; ks < 4; ks++)
                ldsm4(aq[ks], QS + SWZ((w * 16 + lr) * 128 + ks * 32 + lc));
        }

        const uint32_t KB = RING + cur * 16384;
        const uint32_t VB = KB + 8192;

        // S = Q K^T  (already log2-scaled)
        float s[8][4] = {};
        #pragma unroll
        for (int ks = 0; ks < 4; ks++) {
            #pragma unroll
            for (int p = 0; p < 4; p++) {
                uint32_t bh[4];
                ldsm4(bh, KB + SWZ((p * 16 + brr) * 128 + ks * 32 + bcc));
                mma16816(s[2*p],   aq[ks], &bh[0]);
                mma16816(s[2*p+1], aq[ks], &bh[2]);
            }
        }

        // mask-select -> pack -> ex2 (straight-line)
        uint32_t preg[8][2];
        #pragma unroll
        for (int f = 0; f < 8; f++) {
            unsigned wA = (f < 4) ? wa0 : wa1;
            unsigned wB = (f < 4) ? wb0 : wb1;
            int bit = (f & 3) * 8 + t2;
            float xa0 = ((wA >> bit) & 1)       ? s[f][0] : -100.f;
            float xa1 = ((wA >> (bit + 1)) & 1) ? s[f][1] : -100.f;
            float xb0 = ((wB >> bit) & 1)       ? s[f][2] : -100.f;
            float xb1 = ((wB >> (bit + 1)) & 1) ? s[f][3] : -100.f;
            preg[f][0] = h2ex2(packh2(xa0, xa1));
            preg[f][1] = h2ex2(packh2(xb0, xb1));
        }

        // O += P V ; l += P @ ones
        #pragma unroll
        for (int ks = 0; ks < 4; ks++) {
            uint32_t ph[4] = { preg[2*ks][0], preg[2*ks][1],
                               preg[2*ks+1][0], preg[2*ks+1][1] };
            mma16816(lacc, ph, ones_b);
            #pragma unroll
            for (int p = 0; p < 4; p++) {
                uint32_t bh[4];
                ldsm4t(bh, VB + SWZ((ks * 16 + lr) * 128 + p * 32 + lc));
                mma16816(o[2*p],   ph, &bh[0]);
                mma16816(o[2*p+1], ph, &bh[2]);
            }
        }

        cur = (cur == 2) ? 0 : cur + 1;
        pre = (pre == 2) ? 0 : pre + 1;
    }

    // epilogue: l complete per row; normalize, store
    float ia = 1.0f / lacc[0], ib = 1.0f / lacc[2];
    size_t ba = ((size_t)(n * SEQL + qa)) * EMB + h * 64;
    size_t bb = ((size_t)(n * SEQL + qb)) * EMB + h * 64;
    #pragma unroll
    for (int f = 0; f < 8; f++) {
        int col = f * 8 + t2;
        *reinterpret_cast<uint32_t*>(g_ao + ba + col) = packh2(o[f][0] * ia, o[f][1] * ia);
        *reinterpret_cast<uint32_t*>(g_ao + bb + col) = packh2(o[f][2] * ib, o[f][3] * ib);
    }
}

// ---------------------------------------------------------------------------
// Output projection: (8192 x 1024) @ (1024 x 1024)^T + bias, pure fp16 1-term.
// Tile 128x128, 256 threads, K chunks of 64. 3-buffer cp.async ring, ONE
// barrier per tile. smem: 3 x {A 16K | B 16K} = 96K; 2 CTAs/SM (192K < 227K).
// ---------------------------------------------------------------------------
#define OUT_SMEM 98304

__global__ __launch_bounds__(256, 2) void outproj_mma(
    const float* __restrict__ bo, float* __restrict__ out)
{
    extern __shared__ char smc[];
    const uint32_t sb = smem_u32(smc);

    const int m0 = blockIdx.x * 128;
    const int e0 = blockIdx.y * 128;
    const int tid = threadIdx.x;
    const int w = tid >> 5, L = tid & 31;

    // prologue: chunks 0 and 1 -> bufs 0, 1
    #pragma unroll
    for (int pk = 0; pk < 2; pk++) {
        uint32_t B = sb + pk * 32768;
        const int k0 = pk * 64;
        for (int c = tid; c < 1024; c += 256) {
            int r = c >> 3, cb = (c & 7) * 16;
            uint32_t off = SWZ(r * 128 + cb);
            CPA16(B + off,         (const char*)(g_ao + (size_t)(m0 + r) * EMB + k0) + cb);
            CPA16(B + 16384 + off, (const char*)(g_wo + (size_t)(e0 + r) * EMB + k0) + cb);
        }
        CPC();
    }

    float acc[16][4] = {};
    const int lr = (L & 7) + ((L >> 3) & 1) * 8;
    const int lc = ((L >> 4) & 1) * 16;
    const int brr = ((L >> 4) & 1) * 8 + (L & 7);
    const int bcc = ((L >> 3) & 1) * 16;

    int cur = 0, pre = 2;
    for (int kt = 0; kt < 16; kt++) {
        if (kt < 15) { CPW1(); } else { CPW0(); }
        __syncthreads();

        if (kt < 14) {
            uint32_t B = sb + pre * 32768;
            const int k0 = (kt + 2) * 64;
            for (int c = tid; c < 1024; c += 256) {
                int r = c >> 3, cb = (c & 7) * 16;
                uint32_t off = SWZ(r * 128 + cb);
                CPA16(B + off,         (const char*)(g_ao + (size_t)(m0 + r) * EMB + k0) + cb);
                CPA16(B + 16384 + off, (const char*)(g_wo + (size_t)(e0 + r) * EMB + k0) + cb);
            }
            CPC();
        }

        const uint32_t AS = sb + cur * 32768;
        const uint32_t BS = AS + 16384;

        #pragma unroll
        for (int ks = 0; ks < 4; ks++) {
            uint32_t a[4];
            ldsm4(a, AS + SWZ((w * 16 + lr) * 128 + ks * 32 + lc));
            #pragma unroll
            for (int p = 0; p < 8; p++) {
                uint32_t b[4];
                ldsm4(b, BS + SWZ((p * 16 + brr) * 128 + ks * 32 + bcc));
                mma16816(acc[2*p],   a, &b[0]);
                mma16816(acc[2*p+1], a, &b[2]);
            }
        }

        cur = (cur == 2) ? 0 : cur + 1;
        pre = (pre == 2) ? 0 : pre + 1;
    }

    // epilogue
    const int t4 = L >> 2, t2 = (L & 3) * 2;
    const int r0 = m0 + w * 16 + t4, r1 = r0 + 8;
    #pragma unroll
    for (int f = 0; f < 16; f++) {
        int col = e0 + f * 8 + t2;
        float b0v = bo[col], b1v = bo[col + 1];
        float2 v0 = make_float2(acc[f][0] + b0v, acc[f][1] + b1v);
        float2 v1 = make_float2(acc[f][2] + b0v, acc[f][3] + b1v);
        *reinterpret_cast<float2*>(out + (size_t)r0 * EMB + col) = v0;
        *reinterpret_cast<float2*>(out + (size_t)r1 * EMB + col) = v1;
    }
}

// ---------------------------------------------------------------------------
extern "C" void kernel_launch(void* const* d_in, const int* in_sizes, int n_in,
                              void* d_out, int out_size)
{
    const float* values = (const float*)d_in[0];
    const float* keys   = (const float*)d_in[1];
    const float* query  = (const float*)d_in[2];
    const int*   mask   = (const int*)d_in[3];
    const float* Wv     = (const float*)d_in[4];
    const float* Wk     = (const float*)d_in[5];
    const float* Wq     = (const float*)d_in[6];
    const float* Wo     = (const float*)d_in[7];
    const float* bo     = (const float*)d_in[8];
    float* out = (float*)d_out;
    (void)in_sizes; (void)n_in; (void)out_size;

    cudaFuncSetAttribute(front_kernel, cudaFuncAttributeMaxDynamicSharedMemorySize, FRONT_SMEM);
    cudaFuncSetAttribute(attn_mma,     cudaFuncAttributeMaxDynamicSharedMemorySize, ATTN_SMEM);
    cudaFuncSetAttribute(outproj_mma,  cudaFuncAttributeMaxDynamicSharedMemorySize, OUT_SMEM);

    front_kernel<<<dim3(1024, 5), 256, FRONT_SMEM>>>(values, keys, query,
                                                     Wv, Wk, Wq, mask, Wo);
    attn_mma<<<dim3(SEQL/128, NH, NB), 256, ATTN_SMEM>>>();
    outproj_mma<<<dim3(64, 8), 256, OUT_SMEM>>>(bo, out);
}